// round 15
// baseline (speedup 1.0000x reference)
#include <cuda_runtime.h>
#include <cuda_fp16.h>
#include <cstdint>

#define Hh 8
#define LN_EPS 1e-5f
#define SCALE 0.04419417382415922f  // 512^-0.5 (full C, as in source)

// ---------------- scratch (device globals) ----------------------------------
__device__ __half g_xh[(size_t)16384 * 512];      // fp16 x
__device__ __half g_wh[(size_t)3 * 512 * 512];    // fp16 wq|wk|wv
__device__ __half g_qh[(size_t)256 * 512 * 64];   // (b,h,l,d)
__device__ __half g_kh[(size_t)256 * 512 * 64];   // (b,h,l,d)
__device__ __half g_vh[(size_t)256 * 64 * 512];   // (b,h,d,l) transposed V
__device__ __half g_prelnh[(size_t)16384 * 512];  // fp16 pre-LN intermediate

// ---------------- helpers ---------------------------------------------------
__device__ __forceinline__ uint32_t s2u(const void* p) {
    uint32_t a;
    asm("{ .reg .u64 t; cvta.to.shared.u64 t, %1; cvt.u32.u64 %0, t; }" : "=r"(a) : "l"(p));
    return a;
}
__device__ __forceinline__ void cpa16(uint32_t s, const void* g) {
    asm volatile("cp.async.cg.shared.global [%0], [%1], 16;" :: "r"(s), "l"(g));
}
__device__ __forceinline__ void cpa_commit() { asm volatile("cp.async.commit_group;" ::: "memory"); }
template <int N>
__device__ __forceinline__ void cpa_wait() { asm volatile("cp.async.wait_group %0;" :: "n"(N) : "memory"); }

__device__ __forceinline__ void ldm4(uint32_t (&r)[4], uint32_t addr) {
    asm volatile("ldmatrix.sync.aligned.m8n8.x4.shared.b16 {%0,%1,%2,%3}, [%4];"
                 : "=r"(r[0]), "=r"(r[1]), "=r"(r[2]), "=r"(r[3]) : "r"(addr));
}
__device__ __forceinline__ void mma16(float (&c)[4], const uint32_t (&a)[4], const uint32_t* b) {
    asm volatile(
        "mma.sync.aligned.m16n8k16.row.col.f32.f16.f16.f32 "
        "{%0,%1,%2,%3}, {%4,%5,%6,%7}, {%8,%9}, {%0,%1,%2,%3};"
        : "+f"(c[0]), "+f"(c[1]), "+f"(c[2]), "+f"(c[3])
        : "r"(a[0]), "r"(a[1]), "r"(a[2]), "r"(a[3]), "r"(b[0]), "r"(b[1]));
}
__device__ __forceinline__ float4 ldcs4(const float* p) {
    float4 v;
    asm volatile("ld.global.cs.v4.f32 {%0,%1,%2,%3}, [%4];"
                 : "=f"(v.x), "=f"(v.y), "=f"(v.z), "=f"(v.w) : "l"(p));
    return v;
}
__device__ __forceinline__ void stcs4(float* p, float4 v) {
    asm volatile("st.global.cs.v4.f32 [%0], {%1,%2,%3,%4};"
                 :: "l"(p), "f"(v.x), "f"(v.y), "f"(v.z), "f"(v.w) : "memory");
}
__device__ __forceinline__ uint4 cvt8(float4 a, float4 b) {
    __half2 h0 = __float22half2_rn(make_float2(a.x, a.y));
    __half2 h1 = __float22half2_rn(make_float2(a.z, a.w));
    __half2 h2 = __float22half2_rn(make_float2(b.x, b.y));
    __half2 h3 = __float22half2_rn(make_float2(b.z, b.w));
    return make_uint4(*(uint32_t*)&h0, *(uint32_t*)&h1, *(uint32_t*)&h2, *(uint32_t*)&h3);
}

// ---------------- Kernel 0: fp16 convert, 16 floats/thread (MLP=4) -----------
__global__ __launch_bounds__(256) void cvt_all_kernel(
    const float* __restrict__ x, const float* __restrict__ wq,
    const float* __restrict__ wk, const float* __restrict__ wv)
{
    int idx = blockIdx.x * 256 + threadIdx.x;   // 16-float group
    const int XG = 16384 * 512 / 16;            // 524288
    const int WG = 512 * 512 / 16;              // 16384
    const float* srcp; __half* dst;
    if (idx < XG) {
        srcp = x + (size_t)idx * 16;
        dst = g_xh + (size_t)idx * 16;
    } else {
        int j = idx - XG;
        int w = j / WG, r = j - w * WG;
        const float* s = (w == 0) ? wq : (w == 1) ? wk : wv;
        srcp = s + (size_t)r * 16;
        dst = g_wh + ((size_t)w * WG + r) * 16;
    }
    // front-batched independent loads (MLP=4)
    float4 a0 = ldcs4(srcp);
    float4 a1 = ldcs4(srcp + 4);
    float4 a2 = ldcs4(srcp + 8);
    float4 a3 = ldcs4(srcp + 12);
    uint4 o0 = cvt8(a0, a1);
    uint4 o1 = cvt8(a2, a3);
    *(uint4*)dst = o0;
    *(uint4*)(dst + 8) = o1;
}

// ---------------- Kernel 1: QKV projection (fp16 mma, 3-stage pipeline) ------
// CTA 128x128, 8 warps (2m x 4n), warp tile 64x32. K-chunk 64, TRIPLE buffer.
#define QKV_SMEM 110592
__global__ __launch_bounds__(256, 2) void qkv_g(void)
{
    extern __shared__ __half smh[];
    const uint32_t sb = s2u(smh);
    const int tid = threadIdx.x;
    const int lane = tid & 31, warp = tid >> 5;
    const int wm = warp & 1, wn = warp >> 1;
    const int g = lane >> 2, t4 = lane & 3;
    const int which = blockIdx.z;
    const int m0 = blockIdx.y * 128;
    const int n0 = blockIdx.x * 128;

    const __half* __restrict__ A = g_xh + (size_t)m0 * 512;
    const __half* __restrict__ B = g_wh + (size_t)which * 262144 + (size_t)n0 * 512;

    constexpr int A_H = 128 * 72;
    constexpr int STAGE_H = 2 * A_H;

    const uint32_t a_base = (uint32_t)(((wm * 64 + (lane & 15)) * 72 + (lane >> 4) * 8) * 2);
    const uint32_t b_base = (uint32_t)(A_H * 2 +
        (((lane & 7) + (lane >> 4) * 8 + wn * 32) * 72 + ((lane >> 3) & 1) * 8) * 2);

    float acc[4][4][4];
#pragma unroll
    for (int mi = 0; mi < 4; ++mi)
#pragma unroll
        for (int ni = 0; ni < 4; ++ni)
#pragma unroll
            for (int r = 0; r < 4; ++r) acc[mi][ni][r] = 0.f;

    auto load_chunk = [&](int c, int buf) {
        uint32_t base = sb + (uint32_t)(buf * STAGE_H * 2);
#pragma unroll
        for (int i = 0; i < 8; ++i) {
            int idx = tid + i * 256;
            if (idx < 1024) {
                int r = idx >> 3, sg = idx & 7;
                cpa16(base + (uint32_t)((r * 72 + sg * 8) * 2),
                      A + (size_t)r * 512 + c * 64 + sg * 8);
            } else {
                int j = idx - 1024;
                int r = j >> 3, sg = j & 7;
                cpa16(base + (uint32_t)(A_H * 2 + (r * 72 + sg * 8) * 2),
                      B + (size_t)r * 512 + c * 64 + sg * 8);
            }
        }
    };

    load_chunk(0, 0);
    cpa_commit();
    load_chunk(1, 1);
    cpa_commit();

    for (int c = 0; c < 8; ++c) {
        if (c + 2 < 8) load_chunk(c + 2, (c + 2) % 3);
        cpa_commit();
        cpa_wait<2>();
        __syncthreads();
        uint32_t sa = sb + (uint32_t)((c % 3) * STAGE_H * 2);
#pragma unroll
        for (int ks = 0; ks < 4; ++ks) {
            const uint32_t ko = (uint32_t)(ks * 32);
            uint32_t af[4][4], bf0[4], bf1[4];
#pragma unroll
            for (int mi = 0; mi < 4; ++mi)
                ldm4(af[mi], sa + a_base + (uint32_t)(mi * 16 * 72 * 2) + ko);
            ldm4(bf0, sa + b_base + ko);
            ldm4(bf1, sa + b_base + (uint32_t)(16 * 72 * 2) + ko);
#pragma unroll
            for (int mi = 0; mi < 4; ++mi) {
                mma16(acc[mi][0], af[mi], &bf0[0]);
                mma16(acc[mi][1], af[mi], &bf0[2]);
                mma16(acc[mi][2], af[mi], &bf1[0]);
                mma16(acc[mi][3], af[mi], &bf1[2]);
            }
        }
        __syncthreads();
    }

    __half* sT = smh;   // 128 x 136 staging tile
    if (which <= 1) {
#pragma unroll
        for (int mi = 0; mi < 4; ++mi) {
#pragma unroll
            for (int ni = 0; ni < 4; ++ni) {
                int nl = wn * 32 + ni * 8 + 2 * t4;
                int ml = wm * 64 + mi * 16 + g;
                *(__half2*)&sT[ml * 136 + nl] =
                    __float22half2_rn(make_float2(acc[mi][ni][0], acc[mi][ni][1]));
                *(__half2*)&sT[(ml + 8) * 136 + nl] =
                    __float22half2_rn(make_float2(acc[mi][ni][2], acc[mi][ni][3]));
            }
        }
        __syncthreads();
        __half* out = (which == 0) ? g_qh : g_kh;
        int b = m0 >> 9, l0 = m0 & 511;
#pragma unroll
        for (int i = 0; i < 8; ++i) {
            int f = tid + i * 256;
            int row = f >> 4, seg = f & 15;
            uint4 v = *(const uint4*)&sT[row * 136 + seg * 8];
            int h = (n0 >> 6) + (seg >> 3);
            int d = (seg & 7) * 8;
            *(uint4*)&out[((size_t)(b * 8 + h) * 512 + l0 + row) * 64 + d] = v;
        }
    } else {
#pragma unroll
        for (int mi = 0; mi < 4; ++mi) {
#pragma unroll
            for (int ni = 0; ni < 4; ++ni) {
                int nl = wn * 32 + ni * 8 + 2 * t4;
                int ml = wm * 64 + mi * 16 + g;
                sT[nl * 136 + ml]           = __float2half_rn(acc[mi][ni][0]);
                sT[(nl + 1) * 136 + ml]     = __float2half_rn(acc[mi][ni][1]);
                sT[nl * 136 + ml + 8]       = __float2half_rn(acc[mi][ni][2]);
                sT[(nl + 1) * 136 + ml + 8] = __float2half_rn(acc[mi][ni][3]);
            }
        }
        __syncthreads();
        int b = m0 >> 9, l0 = m0 & 511;
#pragma unroll
        for (int i = 0; i < 8; ++i) {
            int f = tid + i * 256;
            int row = f >> 4, seg = f & 15;
            uint4 v = *(const uint4*)&sT[row * 136 + seg * 8];
            int n = n0 + row, h = n >> 6, d = n & 63;
            *(uint4*)&g_vh[(((size_t)(b * 8 + h)) * 64 + d) * 512 + l0 + seg * 8] = v;
        }
    }
}

// ---------------- Kernel 2: fused attention (fp16 S, occupancy 2) ------------
#define ATT_SMEM 114944
#define SS_OFF   9216
#define SKV_OFF  75776
#define SB_OFF   112640
__global__ __launch_bounds__(256, 2) void attn_g(const float* __restrict__ bias_table)
{
    extern __shared__ char smc[];
    const uint32_t sb = s2u(smc);
    const int tid = threadIdx.x;
    const int lane = tid & 31, warp = tid >> 5;
    const int wm = warp & 1, wn = warp >> 1;
    const int g = lane >> 2, t4 = lane & 3;
    const int qb = blockIdx.x;
    const int bh = blockIdx.y;
    const int b = bh >> 3, h = bh & 7;

    const __half* __restrict__ gq = g_qh + (size_t)bh * 32768 + (size_t)qb * 64 * 64;
    const __half* __restrict__ gk = g_kh + (size_t)bh * 32768;
    const __half* __restrict__ gv = g_vh + (size_t)bh * 32768;

    const uint32_t sQ = sb;
    const uint32_t sSb = sb + SS_OFF;
    const uint32_t sKV = sb + SKV_OFF;
    __half* sSh = (__half*)(smc + SS_OFF);
    float* sbias = (float*)(smc + SB_OFF);
    const int woff = 448 - qb * 64;

#pragma unroll
    for (int i = 0; i < 2; ++i) {
        int idx = tid + i * 256;
        int r = idx >> 3, sg = idx & 7;
        cpa16(sQ + (uint32_t)((r * 72 + sg * 8) * 2), gq + (size_t)r * 64 + sg * 8);
    }
#pragma unroll
    for (int i = 0; i < 3; ++i) {
        int j = tid + i * 256;
        if (j < 575) sbias[j] = bias_table[(size_t)(j + woff) * 8 + h];
    }
    cpa_commit();

    auto load_k = [&](int c, int buf) {
        uint32_t base = sKV + (uint32_t)(buf * 18432);
        const __half* src = gk + (size_t)c * 128 * 64;
#pragma unroll
        for (int i = 0; i < 4; ++i) {
            int idx = tid + i * 256;
            int r = idx >> 3, sg = idx & 7;
            cpa16(base + (uint32_t)((r * 72 + sg * 8) * 2), src + (size_t)r * 64 + sg * 8);
        }
    };
    load_k(0, 0);
    cpa_commit();

    const uint32_t aq_base = (uint32_t)(((wm * 32 + (lane & 15)) * 72 + (lane >> 4) * 8) * 2);
    const uint32_t bk_base = (uint32_t)((((lane & 7) + (lane >> 4) * 8 + wn * 32) * 72
                                        + ((lane >> 3) & 1) * 8) * 2);

    for (int c = 0; c < 4; ++c) {
        if (c + 1 < 4) load_k(c + 1, (c + 1) & 1);
        cpa_commit();
        cpa_wait<1>();
        __syncthreads();
        uint32_t skb = sKV + (uint32_t)((c & 1) * 18432);

        float acc[2][4][4];
#pragma unroll
        for (int mi = 0; mi < 2; ++mi)
#pragma unroll
            for (int ni = 0; ni < 4; ++ni)
#pragma unroll
                for (int r = 0; r < 4; ++r) acc[mi][ni][r] = 0.f;

#pragma unroll
        for (int ks = 0; ks < 4; ++ks) {
            const uint32_t ko = (uint32_t)(ks * 32);
            uint32_t af[2][4], bf0[4], bf1[4];
            ldm4(af[0], sQ + aq_base + ko);
            ldm4(af[1], sQ + aq_base + (uint32_t)(16 * 72 * 2) + ko);
            ldm4(bf0, skb + bk_base + ko);
            ldm4(bf1, skb + bk_base + (uint32_t)(16 * 72 * 2) + ko);
#pragma unroll
            for (int mi = 0; mi < 2; ++mi) {
                mma16(acc[mi][0], af[mi], &bf0[0]);
                mma16(acc[mi][1], af[mi], &bf0[2]);
                mma16(acc[mi][2], af[mi], &bf1[0]);
                mma16(acc[mi][3], af[mi], &bf1[2]);
            }
        }
#pragma unroll
        for (int mi = 0; mi < 2; ++mi) {
#pragma unroll
            for (int ni = 0; ni < 4; ++ni) {
                int ml = wm * 32 + mi * 16 + g;
                int col = c * 128 + wn * 32 + ni * 8 + 2 * t4;
                *(__half2*)&sSh[ml * 520 + col] =
                    __float22half2_rn(make_float2(acc[mi][ni][0] * SCALE, acc[mi][ni][1] * SCALE));
                *(__half2*)&sSh[(ml + 8) * 520 + col] =
                    __float22half2_rn(make_float2(acc[mi][ni][2] * SCALE, acc[mi][ni][3] * SCALE));
            }
        }
        __syncthreads();
    }

    auto load_v = [&](int c, int buf) {
        uint32_t base = sKV + (uint32_t)(buf * 18432);
        const __half* src = gv + (size_t)c * 128;
#pragma unroll
        for (int i = 0; i < 4; ++i) {
            int idx = tid + i * 256;
            int r = idx >> 4, sg = idx & 15;
            cpa16(base + (uint32_t)((r * 136 + sg * 8) * 2), src + (size_t)r * 512 + sg * 8);
        }
    };
    load_v(0, 0);
    cpa_commit();

    // softmax (no max-sub: |s| < 1) + post-softmax bias; P fp16 in-place
    {
        const int r0 = warp * 8;
#pragma unroll
        for (int rr = 0; rr < 8; ++rr) {
            const int r = r0 + rr;
            __half2* rowh = (__half2*)(sSh + (size_t)r * 520);
            float vals[16];
            float s = 0.f;
#pragma unroll
            for (int jj = 0; jj < 8; ++jj) {
                float2 fv = __half22float2(rowh[lane + 32 * jj]);
                vals[2 * jj]     = __expf(fv.x);
                vals[2 * jj + 1] = __expf(fv.y);
                s += vals[2 * jj] + vals[2 * jj + 1];
            }
#pragma unroll
            for (int o = 16; o > 0; o >>= 1) s += __shfl_xor_sync(0xffffffffu, s, o);
            float inv = 1.f / s;
            int bbase = 63 - r;
#pragma unroll
            for (int jj = 0; jj < 8; ++jj) {
                int col = 2 * lane + 64 * jj;
                float2 p;
                p.x = vals[2 * jj]     * inv + sbias[bbase + col];
                p.y = vals[2 * jj + 1] * inv + sbias[bbase + col + 1];
                rowh[lane + 32 * jj] = __float22half2_rn(p);
            }
        }
    }
    __syncthreads();

    const uint32_t ap_base = sSb + (uint32_t)(((wm * 32 + (lane & 15)) * 520 + (lane >> 4) * 8) * 2);
    const uint32_t bv_base = (uint32_t)((((lane & 7) + (lane >> 4) * 8 + wn * 16) * 136
                                        + ((lane >> 3) & 1) * 8) * 2);
    float accO[2][2][4];
#pragma unroll
    for (int mi = 0; mi < 2; ++mi)
#pragma unroll
        for (int ni = 0; ni < 2; ++ni)
#pragma unroll
            for (int r = 0; r < 4; ++r) accO[mi][ni][r] = 0.f;

    for (int c = 0; c < 4; ++c) {
        if (c + 1 < 4) load_v(c + 1, (c + 1) & 1);
        cpa_commit();
        cpa_wait<1>();
        __syncthreads();
        uint32_t svb = sKV + (uint32_t)((c & 1) * 18432);

#pragma unroll
        for (int ks = 0; ks < 8; ++ks) {
            const uint32_t kgo = (uint32_t)((c * 128 + ks * 16) * 2);
            const uint32_t ko = (uint32_t)(ks * 32);
            uint32_t af[2][4], bf[4];
            ldm4(af[0], ap_base + kgo);
            ldm4(af[1], ap_base + (uint32_t)(16 * 520 * 2) + kgo);
            ldm4(bf, svb + bv_base + ko);
#pragma unroll
            for (int mi = 0; mi < 2; ++mi) {
                mma16(accO[mi][0], af[mi], &bf[0]);
                mma16(accO[mi][1], af[mi], &bf[2]);
            }
        }
        __syncthreads();
    }

#pragma unroll
    for (int mi = 0; mi < 2; ++mi) {
#pragma unroll
        for (int ni = 0; ni < 2; ++ni) {
            int m = wm * 32 + mi * 16 + g;
            int n = wn * 16 + ni * 8 + 2 * t4;
            size_t rowg = (size_t)(b * 512 + qb * 64 + m);
            *(__half2*)&g_prelnh[rowg * 512 + h * 64 + n] =
                __float22half2_rn(make_float2(accO[mi][ni][0], accO[mi][ni][1]));
            *(__half2*)&g_prelnh[(rowg + 8) * 512 + h * 64 + n] =
                __float22half2_rn(make_float2(accO[mi][ni][2], accO[mi][ni][3]));
        }
    }
}

// ---------------- Kernel 3: LayerNorm (R11 shape + streaming stores) ---------
__global__ __launch_bounds__(256) void ln_kernel(
    const float* __restrict__ gamma, const float* __restrict__ beta,
    float* __restrict__ out)
{
    const int tid = threadIdx.x;
    const int rl = tid >> 6;          // 0..3 row within CTA
    const int ts = tid & 63;          // 64 threads per row, 8 halves each
    const int w = tid >> 5;
    const int row = blockIdx.x * 4 + rl;
    const __half* __restrict__ pr = g_prelnh + (size_t)row * 512;

    uint4 raw = *(const uint4*)(pr + ts * 8);
    __half2 hv[4];
    hv[0] = *(__half2*)&raw.x; hv[1] = *(__half2*)&raw.y;
    hv[2] = *(__half2*)&raw.z; hv[3] = *(__half2*)&raw.w;
    float v[8];
#pragma unroll
    for (int i = 0; i < 4; ++i) {
        float2 f = __half22float2(hv[i]);
        v[2 * i] = f.x; v[2 * i + 1] = f.y;
    }

    __shared__ float red[8], red2[8];
    float s = 0.f, sq = 0.f;
#pragma unroll
    for (int i = 0; i < 8; ++i) { s += v[i]; sq += v[i] * v[i]; }
#pragma unroll
    for (int o = 16; o > 0; o >>= 1) {
        s  += __shfl_xor_sync(0xffffffffu, s, o);
        sq += __shfl_xor_sync(0xffffffffu, sq, o);
    }
    if ((tid & 31) == 0) { red[w] = s; red2[w] = sq; }
    __syncthreads();
    float mu  = (red[rl * 2]  + red[rl * 2 + 1])  * (1.f / 512.f);
    float ex2 = (red2[rl * 2] + red2[rl * 2 + 1]) * (1.f / 512.f);
    float var = ex2 - mu * mu;
    float inv = rsqrtf(var + LN_EPS);

    float4 g0 = *(const float4*)(gamma + ts * 8);
    float4 g1 = *(const float4*)(gamma + ts * 8 + 4);
    float4 b0 = *(const float4*)(beta + ts * 8);
    float4 b1 = *(const float4*)(beta + ts * 8 + 4);
    float4 o0, o1;
    o0.x = g0.x * (v[0] - mu) * inv + b0.x;
    o0.y = g0.y * (v[1] - mu) * inv + b0.y;
    o0.z = g0.z * (v[2] - mu) * inv + b0.z;
    o0.w = g0.w * (v[3] - mu) * inv + b0.w;
    o1.x = g1.x * (v[4] - mu) * inv + b1.x;
    o1.y = g1.y * (v[5] - mu) * inv + b1.y;
    o1.z = g1.z * (v[6] - mu) * inv + b1.z;
    o1.w = g1.w * (v[7] - mu) * inv + b1.w;
    stcs4(out + (size_t)row * 512 + ts * 8, o0);
    stcs4(out + (size_t)row * 512 + ts * 8 + 4, o1);
}

// ---------------------------------------------------------------------------
extern "C" void kernel_launch(void* const* d_in, const int* in_sizes, int n_in,
                              void* d_out, int out_size)
{
    const float* x          = (const float*)d_in[0];
    const float* wq         = (const float*)d_in[1];
    const float* wk         = (const float*)d_in[2];
    const float* wv         = (const float*)d_in[3];
    const float* bias_table = (const float*)d_in[4];
    const float* gamma      = (const float*)d_in[5];
    const float* beta       = (const float*)d_in[6];
    float* out = (float*)d_out;

    cudaFuncSetAttribute(qkv_g,  cudaFuncAttributeMaxDynamicSharedMemorySize, QKV_SMEM);
    cudaFuncSetAttribute(attn_g, cudaFuncAttributeMaxDynamicSharedMemorySize, ATT_SMEM);

    // (8.4M x + 0.8M w) floats / 16 per thread / 256 threads = 2240 blocks
    cvt_all_kernel<<<2240, 256>>>(x, wq, wk, wv);
    qkv_g<<<dim3(4, 128, 3), 256, QKV_SMEM>>>();
    attn_g<<<dim3(8, 256), 256, ATT_SMEM>>>(bias_table);
    ln_kernel<<<4096, 256>>>(gamma, beta, out);
}